// round 4
// baseline (speedup 1.0000x reference)
#include <cuda_runtime.h>
#include <cuda_bf16.h>
#include <cstdint>

#define SEQ   256
#define XDIM  120
#define H     400
#define ZROWS 3200
#define M     200
#define TROWS 257
#define N_ARC  65536
#define N_SIB  200000
#define N_GP   200000
#define N_GSIB 300000

// ---------------- static device scratch (no allocations) ----------------
__device__ float g_x[SEQ * XDIM];        // embedded inputs [s][120]
__device__ float g_z[SEQ * ZROWS];       // z_in both dirs [s][dir*1600 + gate*400 + u]
__device__ float g_states[SEQ * 800];    // [s][ hf(400) | hb(400) ]
__device__ float g_ptab[12 * TROWS * M]; // 12 projection tables, row 256 = null_sib for tabs 7,10
__device__ int   g_flags[64];            // per (dir, block) step counters

// ---------------- helpers ----------------
__device__ __forceinline__ float fast_tanh(float x) {
    // accurate to ~1e-7 abs; used in LSTM recurrence
    return 1.0f - 2.0f / (__expf(2.0f * x) + 1.0f);
}
__device__ __forceinline__ float tanh_ap(float x) {
    float y; asm("tanh.approx.f32 %0, %1;" : "=f"(y) : "f"(x)); return y;
}
__device__ __forceinline__ float fast_sigmoid(float x) {
    return 1.0f / (1.0f + __expf(-x));
}
__device__ __forceinline__ int ld_acq(const int* p) {
    int v;
    asm volatile("ld.acquire.gpu.b32 %0, [%1];" : "=r"(v) : "l"(p) : "memory");
    return v;
}
__device__ __forceinline__ void st_rel(int* p, int v) {
    asm volatile("st.release.gpu.b32 [%0], %1;" :: "l"(p), "r"(v) : "memory");
}

// ---------------- 0. prep: zero flags, write null_sib rows ----------------
__global__ void prep_kernel(const float* __restrict__ null_sib) {
    int t = threadIdx.x;
    if (t < 64) g_flags[t] = 0;
    if (t < M) {
        float v = null_sib[t];
        g_ptab[(7 * TROWS + 256) * M + t]  = v;
        g_ptab[(10 * TROWS + 256) * M + t] = v;
    }
}

// ---------------- 1. embedding concat ----------------
__global__ void embed_kernel(const int* __restrict__ words, const int* __restrict__ tags,
                             const float* __restrict__ wemb, const float* __restrict__ temb) {
    int s = blockIdx.x, j = threadIdx.x;
    if (j < XDIM) {
        float v = (j < 100) ? wemb[words[s] * 100 + j] : temb[tags[s] * 20 + (j - 100)];
        g_x[s * XDIM + j] = v;
    }
}

// ---------------- 2. z_in = Wih @ x + b, both directions (3200 rows x 256 s) ----------------
__global__ __launch_bounds__(256) void zin_kernel(
    const float* __restrict__ Wf, const float* __restrict__ bf,
    const float* __restrict__ Wb, const float* __restrict__ bb) {
    __shared__ float Ws[64][121];
    __shared__ float Xs[32][121];
    int r0 = blockIdx.x * 64;
    int s0 = blockIdx.y * 32;
    int tid = threadIdx.x;

    for (int idx = tid; idx < 64 * 120; idx += 256) {
        int rl = idx / 120, k = idx % 120;
        int r = r0 + rl;
        Ws[rl][k] = (r < 1600) ? Wf[r * 120 + k] : Wb[(r - 1600) * 120 + k];
    }
    for (int idx = tid; idx < 32 * 120; idx += 256) {
        int sl = idx / 120, k = idx % 120;
        Xs[sl][k] = g_x[(s0 + sl) * XDIM + k];
    }
    __syncthreads();

    int tx = tid & 15;   // -> 2 sequence positions
    int ty = tid >> 4;   // -> 4 rows
    float acc[4][2] = {};
    for (int k = 0; k < 120; ++k) {
        float x0 = Xs[tx * 2 + 0][k];
        float x1 = Xs[tx * 2 + 1][k];
#pragma unroll
        for (int i = 0; i < 4; ++i) {
            float w = Ws[ty * 4 + i][k];
            acc[i][0] += w * x0;
            acc[i][1] += w * x1;
        }
    }
#pragma unroll
    for (int i = 0; i < 4; ++i) {
        int r = r0 + ty * 4 + i;
        float bias = (r < 1600) ? bf[r] : bb[r - 1600];
#pragma unroll
        for (int j = 0; j < 2; ++j) {
            int s = s0 + tx * 2 + j;
            g_z[s * ZROWS + r] = acc[i][j] + bias;
        }
    }
}

// ---------------- 3. persistent biLSTM (50 blocks: 25 fwd + 25 bwd) ----------------
// Sync redesign vs R2: per-block release flags (no shared atomic, no threadfence),
// poll fused into the h-load threads, z_in prefetched off the critical path.
__global__ __launch_bounds__(256, 1) void lstm_kernel(
    const float* __restrict__ Whh_f, const float* __restrict__ Whh_b) {
    const int dir = blockIdx.x / 25;        // 0 fwd, 1 bwd
    const int bb  = blockIdx.x % 25;
    const int u0  = bb * 16;                // 16 hidden units per block
    const float* Whh = dir ? Whh_b : Whh_f;

    const int tid   = threadIdx.x;
    const int chunk = tid & 3;              // 4 col chunks of 100
    const int rl    = tid >> 2;             // 0..63 local rows (gate*16 + lu)
    const int gate  = rl >> 4;
    const int lu    = rl & 15;
    const int grow  = gate * 400 + u0 + lu;

    // preload Whh slice into registers: 100 floats / thread
    float4 w[25];
    const float4* wp = (const float4*)(Whh + grow * 400 + chunk * 100);
#pragma unroll
    for (int j = 0; j < 25; ++j) w[j] = wp[j];

    __shared__ __align__(16) float hs[400];
    __shared__ float zs[64];
    float c = 0.0f;  // cell state (meaningful in threads 0..15)

    int* myflag = &g_flags[dir * 32 + bb];
    const int* pollflag = &g_flags[dir * 32 + (tid >> 2)];  // producer of this thread's h segment

    for (int step = 0; step < SEQ; ++step) {
        int s = dir ? (SEQ - 1 - step) : step;

        // prefetch z_in for this step (independent of h -> overlaps poll+load+matvec)
        float zpre0, zpre1, zpre2, zpre3;
        if (tid < 16) {
            const float* zin = g_z + s * ZROWS + dir * 1600 + u0 + tid;
            zpre0 = __ldg(zin);
            zpre1 = __ldg(zin + 400);
            zpre2 = __ldg(zin + 800);
            zpre3 = __ldg(zin + 1200);
        }

        if (step == 0) {
            for (int i = tid; i < 400; i += 256) hs[i] = 0.0f;
        } else if (tid < 100) {
            // wait only for the block that produces THIS thread's 4 h values, then load
            while (ld_acq(pollflag) < step) {}
            int sp = dir ? (s + 1) : (s - 1);
            float4 v = __ldcg((const float4*)(g_states + sp * 800 + dir * 400) + tid);
            ((float4*)hs)[tid] = v;
        }
        __syncthreads();   // bar A: hs complete

        // 64-row x 400 matvec: thread = (row, 100-col chunk)
        const float4* hv = (const float4*)(hs + chunk * 100);
        float ax = 0.f, ay = 0.f, az = 0.f, aw = 0.f;
#pragma unroll
        for (int j = 0; j < 25; ++j) {
            float4 v = hv[j];
            ax += w[j].x * v.x;
            ay += w[j].y * v.y;
            az += w[j].z * v.z;
            aw += w[j].w * v.w;
        }
        float val = (ax + ay) + (az + aw);
        val += __shfl_xor_sync(0xFFFFFFFFu, val, 1);
        val += __shfl_xor_sync(0xFFFFFFFFu, val, 2);
        if (chunk == 0) zs[rl] = val;
        __syncthreads();   // bar B: zs complete, hs reads complete

        if (tid < 16) {
            float zi = zs[0 * 16 + tid] + zpre0;
            float zf = zs[1 * 16 + tid] + zpre1;
            float zg = zs[2 * 16 + tid] + zpre2;
            float zo = zs[3 * 16 + tid] + zpre3;
            float iv = fast_sigmoid(zi);
            float fv = fast_sigmoid(zf);
            float gv = fast_tanh(zg);
            float ov = fast_sigmoid(zo);
            c = fv * c + iv * gv;
            float h = ov * fast_tanh(c);
            __stcg(g_states + s * 800 + dir * 400 + u0 + tid, h);
            __syncwarp(0x0000FFFFu);   // order the 16 h stores before the release
            if (tid == 0) st_rel(myflag, step + 1);
        }
        // no trailing block barrier needed: hs/zs rewrites next step are fenced by bar A/B
    }
}

// ---------------- 4. 12 projections: ptab[p][s][m] = sum_d W_proj[p][m][d]*states[s][d] ----------------
__global__ __launch_bounds__(224) void proj_kernel(const float* __restrict__ W_proj) {
    extern __shared__ float sm[];
    float* ws = sm;            // [100 k][200 m]
    float* st = sm + 20000;    // [16 s][100 k]

    const int p   = blockIdx.x;
    const int s0  = blockIdx.y * 16;
    const int tid = threadIdx.x;

    float acc[16];
#pragma unroll
    for (int i = 0; i < 16; ++i) acc[i] = 0.0f;

    for (int dc = 0; dc < 8; ++dc) {
        __syncthreads();
        for (int idx = tid; idx < 20000; idx += 224) {
            int m = idx / 100, k = idx % 100;
            ws[k * 200 + m] = W_proj[(p * 200 + m) * 800 + dc * 100 + k];
        }
        for (int idx = tid; idx < 1600; idx += 224) {
            int sl = idx / 100, k = idx % 100;
            st[sl * 100 + k] = g_states[(s0 + sl) * 800 + dc * 100 + k];
        }
        __syncthreads();

        if (tid < 200) {
            for (int k = 0; k < 100; k += 4) {
                float w0 = ws[(k + 0) * 200 + tid];
                float w1 = ws[(k + 1) * 200 + tid];
                float w2 = ws[(k + 2) * 200 + tid];
                float w3 = ws[(k + 3) * 200 + tid];
#pragma unroll
                for (int sl = 0; sl < 16; ++sl) {
                    float4 v = *(const float4*)(st + sl * 100 + k);
                    acc[sl] += w0 * v.x + w1 * v.y + w2 * v.z + w3 * v.w;
                }
            }
        }
    }
    if (tid < 200) {
#pragma unroll
        for (int sl = 0; sl < 16; ++sl)
            g_ptab[(p * TROWS + s0 + sl) * M + tid] = acc[sl];
    }
}

// ---------------- 5. scoring: warp per score (4 scores / warp) ----------------
template <int NR>
__device__ __forceinline__ float warp_score(const float* __restrict__ wsrow,
                                            const float* r0, const float* r1,
                                            const float* r2, const float* r3, int lane) {
    float acc = 0.0f;
#pragma unroll
    for (int it = 0; it < 4; ++it) {
        int m2 = it * 32 + lane;  // float2 index, valid < 100
        if (m2 < 100) {
            float2 a = ((const float2*)r0)[m2];
            float2 b = ((const float2*)r1)[m2];
            float sx = a.x + b.x, sy = a.y + b.y;
            if (NR > 2) {
                float2 cc = ((const float2*)r2)[m2];
                sx += cc.x; sy += cc.y;
            }
            if (NR > 3) {
                float2 d = ((const float2*)r3)[m2];
                sx += d.x; sy += d.y;
            }
            float2 w = ((const float2*)wsrow)[m2];
            acc += tanh_ap(sx) * w.x + tanh_ap(sy) * w.y;
        }
    }
    acc += __shfl_xor_sync(0xFFFFFFFFu, acc, 16);
    acc += __shfl_xor_sync(0xFFFFFFFFu, acc, 8);
    acc += __shfl_xor_sync(0xFFFFFFFFu, acc, 4);
    acc += __shfl_xor_sync(0xFFFFFFFFu, acc, 2);
    acc += __shfl_xor_sync(0xFFFFFFFFu, acc, 1);
    return acc;
}

#define GA (N_ARC / 4)
#define GS (N_SIB / 4)
#define GG (N_GP / 4)
#define GX (N_GSIB / 4)
#define TOTAL_GROUPS (GA + GS + GG + GX)

__global__ __launch_bounds__(256) void score_kernel(
    const int* __restrict__ arc_head, const int* __restrict__ arc_mod,
    const int* __restrict__ sib_head, const int* __restrict__ sib_mod, const int* __restrict__ sib_sib,
    const int* __restrict__ gp_head,  const int* __restrict__ gp_mod,  const int* __restrict__ gp_grand,
    const int* __restrict__ gsib_head, const int* __restrict__ gsib_mod,
    const int* __restrict__ gsib_sib,  const int* __restrict__ gsib_grand,
    const float* __restrict__ W_score, float* __restrict__ out) {
    int gw   = (blockIdx.x * blockDim.x + threadIdx.x) >> 5;
    int lane = threadIdx.x & 31;
    if (gw >= TOTAL_GROUPS) return;

    const float* tab = g_ptab;
    const float* t0 = tab + 0  * TROWS * M;
    const float* t1 = tab + 1  * TROWS * M;
    const float* t2 = tab + 2  * TROWS * M;
    const float* t3 = tab + 3  * TROWS * M;
    const float* t4 = tab + 4  * TROWS * M;
    const float* t5 = tab + 5  * TROWS * M;
    const float* t6 = tab + 6  * TROWS * M;
    const float* t7 = tab + 7  * TROWS * M;
    const float* t8 = tab + 8  * TROWS * M;
    const float* t9 = tab + 9  * TROWS * M;
    const float* t10 = tab + 10 * TROWS * M;
    const float* t11 = tab + 11 * TROWS * M;

    if (gw < GA) {
        int base = gw * 4;
#pragma unroll
        for (int k = 0; k < 4; ++k) {
            int i = base + k;
            float sc = warp_score<2>(W_score + 0 * M,
                                     t0 + arc_head[i] * M, t1 + arc_mod[i] * M,
                                     t0, t0, lane);
            if (lane == 0) out[i] = sc;
        }
    } else if (gw < GA + GS) {
        int base = (gw - GA) * 4;
#pragma unroll
        for (int k = 0; k < 4; ++k) {
            int i = base + k;
            float sc = warp_score<3>(W_score + 1 * M,
                                     t5 + sib_head[i] * M, t6 + sib_mod[i] * M,
                                     t7 + sib_sib[i] * M, t0, lane);
            if (lane == 0) out[N_ARC + i] = sc;
        }
    } else if (gw < GA + GS + GG) {
        int base = (gw - GA - GS) * 4;
#pragma unroll
        for (int k = 0; k < 4; ++k) {
            int i = base + k;
            float sc = warp_score<3>(W_score + 2 * M,
                                     t3 + gp_head[i] * M, t4 + gp_mod[i] * M,
                                     t2 + gp_grand[i] * M, t0, lane);
            if (lane == 0) out[N_ARC + N_SIB + i] = sc;
        }
    } else {
        int base = (gw - GA - GS - GG) * 4;
#pragma unroll
        for (int k = 0; k < 4; ++k) {
            int i = base + k;
            float sc = warp_score<4>(W_score + 3 * M,
                                     t8 + gsib_head[i] * M, t9 + gsib_mod[i] * M,
                                     t10 + gsib_sib[i] * M, t11 + gsib_grand[i] * M, lane);
            if (lane == 0) out[N_ARC + N_SIB + N_GP + i] = sc;
        }
    }
}

// ---------------- launch ----------------
extern "C" void kernel_launch(void* const* d_in, const int* in_sizes, int n_in,
                              void* d_out, int out_size) {
    const int*   words      = (const int*)d_in[0];
    const int*   tags       = (const int*)d_in[1];
    const int*   arc_head   = (const int*)d_in[2];
    const int*   arc_mod    = (const int*)d_in[3];
    const int*   sib_head   = (const int*)d_in[4];
    const int*   sib_mod    = (const int*)d_in[5];
    const int*   sib_sib    = (const int*)d_in[6];
    const int*   gp_head    = (const int*)d_in[7];
    const int*   gp_mod     = (const int*)d_in[8];
    const int*   gp_grand   = (const int*)d_in[9];
    const int*   gsib_head  = (const int*)d_in[10];
    const int*   gsib_mod   = (const int*)d_in[11];
    const int*   gsib_sib   = (const int*)d_in[12];
    const int*   gsib_grand = (const int*)d_in[13];
    const float* word_emb   = (const float*)d_in[14];
    const float* tag_emb    = (const float*)d_in[15];
    const float* Wih_f      = (const float*)d_in[16];
    const float* Whh_f      = (const float*)d_in[17];
    const float* b_f        = (const float*)d_in[18];
    const float* Wih_b      = (const float*)d_in[19];
    const float* Whh_b      = (const float*)d_in[20];
    const float* b_b        = (const float*)d_in[21];
    const float* W_proj     = (const float*)d_in[22];
    const float* W_score    = (const float*)d_in[23];
    const float* null_sib   = (const float*)d_in[24];
    float* out = (float*)d_out;

    static bool attr_done = false;
    if (!attr_done) {
        cudaFuncSetAttribute(proj_kernel, cudaFuncAttributeMaxDynamicSharedMemorySize, 90112);
        attr_done = true;
    }

    prep_kernel<<<1, 512>>>(null_sib);
    embed_kernel<<<SEQ, 128>>>(words, tags, word_emb, tag_emb);
    zin_kernel<<<dim3(50, 8), 256>>>(Wih_f, b_f, Wih_b, b_b);
    lstm_kernel<<<50, 256>>>(Whh_f, Whh_b);
    proj_kernel<<<dim3(12, 16), 224, 86400>>>(W_proj);
    score_kernel<<<(TOTAL_GROUPS + 7) / 8, 256>>>(
        arc_head, arc_mod, sib_head, sib_mod, sib_sib,
        gp_head, gp_mod, gp_grand,
        gsib_head, gsib_mod, gsib_sib, gsib_grand,
        W_score, out);
}

// round 6
// speedup vs baseline: 1.6014x; 1.6014x over previous
#include <cuda_runtime.h>
#include <cuda_bf16.h>
#include <cstdint>

#define SEQ   256
#define XDIM  120
#define H     400
#define ZROWS 3200
#define M     200
#define TROWS 257
#define N_ARC  65536
#define N_SIB  200000
#define N_GP   200000
#define N_GSIB 300000

// ---------------- static device scratch (no allocations) ----------------
__device__ float g_x[SEQ * XDIM];        // embedded inputs [s][120]
__device__ float g_z[SEQ * ZROWS];       // z_in both dirs [s][dir*1600 + gate*400 + u]
__device__ float g_states[SEQ * 800];    // [s][ hf(400) | hb(400) ]
__device__ float g_ptab[12 * TROWS * M]; // 12 projection tables, row 256 = null_sib for tabs 7,10
__device__ int   g_flags[50 * 32];       // per (dir,block) step counters, ONE PER 128B LINE

// ---------------- helpers ----------------
__device__ __forceinline__ float fast_tanh(float x) {
    return 1.0f - 2.0f / (__expf(2.0f * x) + 1.0f);
}
__device__ __forceinline__ float tanh_ap(float x) {
    float y; asm("tanh.approx.f32 %0, %1;" : "=f"(y) : "f"(x)); return y;
}
__device__ __forceinline__ float fast_sigmoid(float x) {
    return 1.0f / (1.0f + __expf(-x));
}
__device__ __forceinline__ int ld_acq(const int* p) {
    int v;
    asm volatile("ld.acquire.gpu.b32 %0, [%1];" : "=r"(v) : "l"(p) : "memory");
    return v;
}
__device__ __forceinline__ void st_rel(int* p, int v) {
    asm volatile("st.release.gpu.b32 [%0], %1;" :: "l"(p), "r"(v) : "memory");
}

// ---------------- 0. prep: zero flags, write null_sib rows ----------------
__global__ void prep_kernel(const float* __restrict__ null_sib) {
    int t = threadIdx.x;
    for (int i = t; i < 50 * 32; i += blockDim.x) g_flags[i] = 0;
    if (t < M) {
        float v = null_sib[t];
        g_ptab[(7 * TROWS + 256) * M + t]  = v;
        g_ptab[(10 * TROWS + 256) * M + t] = v;
    }
}

// ---------------- 1. embedding concat ----------------
__global__ void embed_kernel(const int* __restrict__ words, const int* __restrict__ tags,
                             const float* __restrict__ wemb, const float* __restrict__ temb) {
    int s = blockIdx.x, j = threadIdx.x;
    if (j < XDIM) {
        float v = (j < 100) ? wemb[words[s] * 100 + j] : temb[tags[s] * 20 + (j - 100)];
        g_x[s * XDIM + j] = v;
    }
}

// ---------------- 2. z_in = Wih @ x + b, both directions (3200 rows x 256 s) ----------------
__global__ __launch_bounds__(256) void zin_kernel(
    const float* __restrict__ Wf, const float* __restrict__ bf,
    const float* __restrict__ Wb, const float* __restrict__ bb) {
    __shared__ float Ws[64][121];
    __shared__ float Xs[32][121];
    int r0 = blockIdx.x * 64;
    int s0 = blockIdx.y * 32;
    int tid = threadIdx.x;

    for (int idx = tid; idx < 64 * 120; idx += 256) {
        int rl = idx / 120, k = idx % 120;
        int r = r0 + rl;
        Ws[rl][k] = (r < 1600) ? Wf[r * 120 + k] : Wb[(r - 1600) * 120 + k];
    }
    for (int idx = tid; idx < 32 * 120; idx += 256) {
        int sl = idx / 120, k = idx % 120;
        Xs[sl][k] = g_x[(s0 + sl) * XDIM + k];
    }
    __syncthreads();

    int tx = tid & 15;   // -> 2 sequence positions
    int ty = tid >> 4;   // -> 4 rows
    float acc[4][2] = {};
    for (int k = 0; k < 120; ++k) {
        float x0 = Xs[tx * 2 + 0][k];
        float x1 = Xs[tx * 2 + 1][k];
#pragma unroll
        for (int i = 0; i < 4; ++i) {
            float w = Ws[ty * 4 + i][k];
            acc[i][0] += w * x0;
            acc[i][1] += w * x1;
        }
    }
#pragma unroll
    for (int i = 0; i < 4; ++i) {
        int r = r0 + ty * 4 + i;
        float bias = (r < 1600) ? bf[r] : bb[r - 1600];
#pragma unroll
        for (int j = 0; j < 2; ++j) {
            int s = s0 + tx * 2 + j;
            g_z[s * ZROWS + r] = acc[i][j] + bias;
        }
    }
}

// ---------------- 3. persistent biLSTM (50 blocks: 25 fwd + 25 bwd) ----------------
// R5: per-block flags padded to one 128B line each; fused per-segment polling.
__global__ __launch_bounds__(256, 1) void lstm_kernel(
    const float* __restrict__ Whh_f, const float* __restrict__ Whh_b) {
    const int dir = blockIdx.x / 25;        // 0 fwd, 1 bwd
    const int bb  = blockIdx.x % 25;
    const int u0  = bb * 16;                // 16 hidden units per block
    const float* Whh = dir ? Whh_b : Whh_f;

    const int tid   = threadIdx.x;
    const int chunk = tid & 3;              // 4 col chunks of 100
    const int rl    = tid >> 2;             // 0..63 local rows (gate*16 + lu)
    const int gate  = rl >> 4;
    const int lu    = rl & 15;
    const int grow  = gate * 400 + u0 + lu;

    // preload Whh slice into registers: 100 floats / thread
    float4 w[25];
    const float4* wp = (const float4*)(Whh + grow * 400 + chunk * 100);
#pragma unroll
    for (int j = 0; j < 25; ++j) w[j] = wp[j];

    __shared__ __align__(16) float hs[400];
    __shared__ float zs[64];
    float c = 0.0f;  // cell state (meaningful in threads 0..15)

    int* myflag = &g_flags[(dir * 25 + bb) * 32];
    const int* pollflag = &g_flags[(dir * 25 + (tid >> 2)) * 32];  // producer of this thread's segment

    for (int step = 0; step < SEQ; ++step) {
        int s = dir ? (SEQ - 1 - step) : step;

        // prefetch z_in for this step (independent of h -> overlaps poll+load+matvec)
        float zpre0, zpre1, zpre2, zpre3;
        if (tid < 16) {
            const float* zin = g_z + s * ZROWS + dir * 1600 + u0 + tid;
            zpre0 = __ldg(zin);
            zpre1 = __ldg(zin + 400);
            zpre2 = __ldg(zin + 800);
            zpre3 = __ldg(zin + 1200);
        }

        if (step == 0) {
            for (int i = tid; i < 400; i += 256) hs[i] = 0.0f;
        } else if (tid < 100) {
            // wait only for the block producing THIS thread's 4 h values, then load
            while (ld_acq(pollflag) < step) {}
            int sp = dir ? (s + 1) : (s - 1);
            float4 v = __ldcg((const float4*)(g_states + sp * 800 + dir * 400) + tid);
            ((float4*)hs)[tid] = v;
        }
        __syncthreads();   // bar A: hs complete

        // 64-row x 400 matvec: thread = (row, 100-col chunk)
        const float4* hv = (const float4*)(hs + chunk * 100);
        float ax = 0.f, ay = 0.f, az = 0.f, aw = 0.f;
#pragma unroll
        for (int j = 0; j < 25; ++j) {
            float4 v = hv[j];
            ax += w[j].x * v.x;
            ay += w[j].y * v.y;
            az += w[j].z * v.z;
            aw += w[j].w * v.w;
        }
        float val = (ax + ay) + (az + aw);
        val += __shfl_xor_sync(0xFFFFFFFFu, val, 1);
        val += __shfl_xor_sync(0xFFFFFFFFu, val, 2);
        if (chunk == 0) zs[rl] = val;
        __syncthreads();   // bar B: zs complete, hs reads complete

        if (tid < 16) {
            float zi = zs[0 * 16 + tid] + zpre0;
            float zf = zs[1 * 16 + tid] + zpre1;
            float zg = zs[2 * 16 + tid] + zpre2;
            float zo = zs[3 * 16 + tid] + zpre3;
            float iv = fast_sigmoid(zi);
            float fv = fast_sigmoid(zf);
            float gv = fast_tanh(zg);
            float ov = fast_sigmoid(zo);
            c = fv * c + iv * gv;
            float h = ov * fast_tanh(c);
            __stcg(g_states + s * 800 + dir * 400 + u0 + tid, h);
            __syncwarp(0x0000FFFFu);   // order the 16 h stores before the release
            if (tid == 0) st_rel(myflag, step + 1);
        }
    }
}

// ---------------- 4. 12 projections: ptab[p][s][m] = sum_d W_proj[p][m][d]*states[s][d] ----------------
__global__ __launch_bounds__(224) void proj_kernel(const float* __restrict__ W_proj) {
    extern __shared__ float sm[];
    float* ws = sm;            // [100 k][200 m]
    float* st = sm + 20000;    // [16 s][100 k]

    const int p   = blockIdx.x;
    const int s0  = blockIdx.y * 16;
    const int tid = threadIdx.x;

    float acc[16];
#pragma unroll
    for (int i = 0; i < 16; ++i) acc[i] = 0.0f;

    for (int dc = 0; dc < 8; ++dc) {
        __syncthreads();
        for (int idx = tid; idx < 20000; idx += 224) {
            int m = idx / 100, k = idx % 100;
            ws[k * 200 + m] = W_proj[(p * 200 + m) * 800 + dc * 100 + k];
        }
        for (int idx = tid; idx < 1600; idx += 224) {
            int sl = idx / 100, k = idx % 100;
            st[sl * 100 + k] = g_states[(s0 + sl) * 800 + dc * 100 + k];
        }
        __syncthreads();

        if (tid < 200) {
            for (int k = 0; k < 100; k += 4) {
                float w0 = ws[(k + 0) * 200 + tid];
                float w1 = ws[(k + 1) * 200 + tid];
                float w2 = ws[(k + 2) * 200 + tid];
                float w3 = ws[(k + 3) * 200 + tid];
#pragma unroll
                for (int sl = 0; sl < 16; ++sl) {
                    float4 v = *(const float4*)(st + sl * 100 + k);
                    acc[sl] += w0 * v.x + w1 * v.y + w2 * v.z + w3 * v.w;
                }
            }
        }
    }
    if (tid < 200) {
#pragma unroll
        for (int sl = 0; sl < 16; ++sl)
            g_ptab[(p * TROWS + s0 + sl) * M + tid] = acc[sl];
    }
}

// ---------------- 5. scoring: warp per score (4 scores / warp) ----------------
template <int NR>
__device__ __forceinline__ float warp_score(const float* __restrict__ wsrow,
                                            const float* r0, const float* r1,
                                            const float* r2, const float* r3, int lane) {
    float acc = 0.0f;
#pragma unroll
    for (int it = 0; it < 4; ++it) {
        int m2 = it * 32 + lane;  // float2 index, valid < 100
        if (m2 < 100) {
            float2 a = ((const float2*)r0)[m2];
            float2 b = ((const float2*)r1)[m2];
            float sx = a.x + b.x, sy = a.y + b.y;
            if (NR > 2) {
                float2 cc = ((const float2*)r2)[m2];
                sx += cc.x; sy += cc.y;
            }
            if (NR > 3) {
                float2 d = ((const float2*)r3)[m2];
                sx += d.x; sy += d.y;
            }
            float2 w = ((const float2*)wsrow)[m2];
            acc += tanh_ap(sx) * w.x + tanh_ap(sy) * w.y;
        }
    }
    acc += __shfl_xor_sync(0xFFFFFFFFu, acc, 16);
    acc += __shfl_xor_sync(0xFFFFFFFFu, acc, 8);
    acc += __shfl_xor_sync(0xFFFFFFFFu, acc, 4);
    acc += __shfl_xor_sync(0xFFFFFFFFu, acc, 2);
    acc += __shfl_xor_sync(0xFFFFFFFFu, acc, 1);
    return acc;
}

#define GA (N_ARC / 4)
#define GS (N_SIB / 4)
#define GG (N_GP / 4)
#define GX (N_GSIB / 4)
#define TOTAL_GROUPS (GA + GS + GG + GX)

__global__ __launch_bounds__(256) void score_kernel(
    const int* __restrict__ arc_head, const int* __restrict__ arc_mod,
    const int* __restrict__ sib_head, const int* __restrict__ sib_mod, const int* __restrict__ sib_sib,
    const int* __restrict__ gp_head,  const int* __restrict__ gp_mod,  const int* __restrict__ gp_grand,
    const int* __restrict__ gsib_head, const int* __restrict__ gsib_mod,
    const int* __restrict__ gsib_sib,  const int* __restrict__ gsib_grand,
    const float* __restrict__ W_score, float* __restrict__ out) {
    int gw   = (blockIdx.x * blockDim.x + threadIdx.x) >> 5;
    int lane = threadIdx.x & 31;
    if (gw >= TOTAL_GROUPS) return;

    const float* tab = g_ptab;
    const float* t0 = tab + 0  * TROWS * M;
    const float* t1 = tab + 1  * TROWS * M;
    const float* t2 = tab + 2  * TROWS * M;
    const float* t3 = tab + 3  * TROWS * M;
    const float* t4 = tab + 4  * TROWS * M;
    const float* t5 = tab + 5  * TROWS * M;
    const float* t6 = tab + 6  * TROWS * M;
    const float* t7 = tab + 7  * TROWS * M;
    const float* t8 = tab + 8  * TROWS * M;
    const float* t9 = tab + 9  * TROWS * M;
    const float* t10 = tab + 10 * TROWS * M;
    const float* t11 = tab + 11 * TROWS * M;

    if (gw < GA) {
        int base = gw * 4;
#pragma unroll
        for (int k = 0; k < 4; ++k) {
            int i = base + k;
            float sc = warp_score<2>(W_score + 0 * M,
                                     t0 + arc_head[i] * M, t1 + arc_mod[i] * M,
                                     t0, t0, lane);
            if (lane == 0) out[i] = sc;
        }
    } else if (gw < GA + GS) {
        int base = (gw - GA) * 4;
#pragma unroll
        for (int k = 0; k < 4; ++k) {
            int i = base + k;
            float sc = warp_score<3>(W_score + 1 * M,
                                     t5 + sib_head[i] * M, t6 + sib_mod[i] * M,
                                     t7 + sib_sib[i] * M, t0, lane);
            if (lane == 0) out[N_ARC + i] = sc;
        }
    } else if (gw < GA + GS + GG) {
        int base = (gw - GA - GS) * 4;
#pragma unroll
        for (int k = 0; k < 4; ++k) {
            int i = base + k;
            float sc = warp_score<3>(W_score + 2 * M,
                                     t3 + gp_head[i] * M, t4 + gp_mod[i] * M,
                                     t2 + gp_grand[i] * M, t0, lane);
            if (lane == 0) out[N_ARC + N_SIB + i] = sc;
        }
    } else {
        int base = (gw - GA - GS - GG) * 4;
#pragma unroll
        for (int k = 0; k < 4; ++k) {
            int i = base + k;
            float sc = warp_score<4>(W_score + 3 * M,
                                     t8 + gsib_head[i] * M, t9 + gsib_mod[i] * M,
                                     t10 + gsib_sib[i] * M, t11 + gsib_grand[i] * M, lane);
            if (lane == 0) out[N_ARC + N_SIB + N_GP + i] = sc;
        }
    }
}

// ---------------- launch ----------------
extern "C" void kernel_launch(void* const* d_in, const int* in_sizes, int n_in,
                              void* d_out, int out_size) {
    const int*   words      = (const int*)d_in[0];
    const int*   tags       = (const int*)d_in[1];
    const int*   arc_head   = (const int*)d_in[2];
    const int*   arc_mod    = (const int*)d_in[3];
    const int*   sib_head   = (const int*)d_in[4];
    const int*   sib_mod    = (const int*)d_in[5];
    const int*   sib_sib    = (const int*)d_in[6];
    const int*   gp_head    = (const int*)d_in[7];
    const int*   gp_mod     = (const int*)d_in[8];
    const int*   gp_grand   = (const int*)d_in[9];
    const int*   gsib_head  = (const int*)d_in[10];
    const int*   gsib_mod   = (const int*)d_in[11];
    const int*   gsib_sib   = (const int*)d_in[12];
    const int*   gsib_grand = (const int*)d_in[13];
    const float* word_emb   = (const float*)d_in[14];
    const float* tag_emb    = (const float*)d_in[15];
    const float* Wih_f      = (const float*)d_in[16];
    const float* Whh_f      = (const float*)d_in[17];
    const float* b_f        = (const float*)d_in[18];
    const float* Wih_b      = (const float*)d_in[19];
    const float* Whh_b      = (const float*)d_in[20];
    const float* b_b        = (const float*)d_in[21];
    const float* W_proj     = (const float*)d_in[22];
    const float* W_score    = (const float*)d_in[23];
    const float* null_sib   = (const float*)d_in[24];
    float* out = (float*)d_out;

    static bool attr_done = false;
    if (!attr_done) {
        cudaFuncSetAttribute(proj_kernel, cudaFuncAttributeMaxDynamicSharedMemorySize, 90112);
        attr_done = true;
    }

    prep_kernel<<<1, 512>>>(null_sib);
    embed_kernel<<<SEQ, 128>>>(words, tags, word_emb, tag_emb);
    zin_kernel<<<dim3(50, 8), 256>>>(Wih_f, b_f, Wih_b, b_b);
    lstm_kernel<<<50, 256>>>(Whh_f, Whh_b);
    proj_kernel<<<dim3(12, 16), 224, 86400>>>(W_proj);
    score_kernel<<<(TOTAL_GROUPS + 7) / 8, 256>>>(
        arc_head, arc_mod, sib_head, sib_mod, sib_sib,
        gp_head, gp_mod, gp_grand,
        gsib_head, gsib_mod, gsib_sib, gsib_grand,
        W_score, out);
}

// round 8
// speedup vs baseline: 2.1303x; 1.3302x over previous
#include <cuda_runtime.h>
#include <cuda_bf16.h>
#include <cstdint>

#define SEQ   256
#define XDIM  120
#define H     400
#define ZROWS 3200
#define M     200
#define TROWS 257
#define N_ARC  65536
#define N_SIB  200000
#define N_GP   200000
#define N_GSIB 300000
#define NCLUST 16          // CTAs per direction (one cluster each)
#define UPC    25          // hidden units per CTA (400/16)

// ---------------- static device scratch (no allocations) ----------------
__device__ float g_x[SEQ * XDIM];        // embedded inputs [s][120]
__device__ float g_z[SEQ * ZROWS];       // z_in both dirs [s][dir*1600 + gate*400 + u]
__device__ float g_states[SEQ * 800];    // [s][ hf(400) | hb(400) ]
__device__ float g_ptab[12 * TROWS * M]; // 12 projection tables, row 256 = null_sib for tabs 7,10

// ---------------- helpers ----------------
__device__ __forceinline__ float fast_tanh(float x) {
    return 1.0f - 2.0f / (__expf(2.0f * x) + 1.0f);
}
__device__ __forceinline__ float tanh_ap(float x) {
    float y; asm("tanh.approx.f32 %0, %1;" : "=f"(y) : "f"(x)); return y;
}
__device__ __forceinline__ float fast_sigmoid(float x) {
    return 1.0f / (1.0f + __expf(-x));
}
__device__ __forceinline__ uint32_t smem_u32(const void* p) {
    uint32_t a;
    asm("{ .reg .u64 t; cvta.to.shared.u64 t, %1; cvt.u32.u64 %0, t; }" : "=r"(a) : "l"(p));
    return a;
}
__device__ __forceinline__ void st_dsmem_f32(uint32_t local_addr, uint32_t rank, float v) {
    uint32_t remote;
    asm volatile("mapa.shared::cluster.u32 %0, %1, %2;" : "=r"(remote) : "r"(local_addr), "r"(rank));
    asm volatile("st.shared::cluster.f32 [%0], %1;" :: "r"(remote), "f"(v) : "memory");
}
__device__ __forceinline__ void cluster_sync_() {
    asm volatile("barrier.cluster.arrive.aligned;" ::: "memory");
    asm volatile("barrier.cluster.wait.aligned;" ::: "memory");
}
__device__ __forceinline__ uint32_t ctarank_() {
    uint32_t r; asm("mov.u32 %0, %%cluster_ctarank;" : "=r"(r)); return r;
}

// ---------------- 0. prep: write null_sib rows ----------------
__global__ void prep_kernel(const float* __restrict__ null_sib) {
    int t = threadIdx.x;
    if (t < M) {
        float v = null_sib[t];
        g_ptab[(7 * TROWS + 256) * M + t]  = v;
        g_ptab[(10 * TROWS + 256) * M + t] = v;
    }
}

// ---------------- 1. embedding concat ----------------
__global__ void embed_kernel(const int* __restrict__ words, const int* __restrict__ tags,
                             const float* __restrict__ wemb, const float* __restrict__ temb) {
    int s = blockIdx.x, j = threadIdx.x;
    if (j < XDIM) {
        float v = (j < 100) ? wemb[words[s] * 100 + j] : temb[tags[s] * 20 + (j - 100)];
        g_x[s * XDIM + j] = v;
    }
}

// ---------------- 2. z_in = Wih @ x + b, both directions (3200 rows x 256 s) ----------------
__global__ __launch_bounds__(256) void zin_kernel(
    const float* __restrict__ Wf, const float* __restrict__ bf,
    const float* __restrict__ Wb, const float* __restrict__ bb) {
    __shared__ float Ws[64][121];
    __shared__ float Xs[32][121];
    int r0 = blockIdx.x * 64;
    int s0 = blockIdx.y * 32;
    int tid = threadIdx.x;

    for (int idx = tid; idx < 64 * 120; idx += 256) {
        int rl = idx / 120, k = idx % 120;
        int r = r0 + rl;
        Ws[rl][k] = (r < 1600) ? Wf[r * 120 + k] : Wb[(r - 1600) * 120 + k];
    }
    for (int idx = tid; idx < 32 * 120; idx += 256) {
        int sl = idx / 120, k = idx % 120;
        Xs[sl][k] = g_x[(s0 + sl) * XDIM + k];
    }
    __syncthreads();

    int tx = tid & 15;   // -> 2 sequence positions
    int ty = tid >> 4;   // -> 4 rows
    float acc[4][2] = {};
    for (int k = 0; k < 120; ++k) {
        float x0 = Xs[tx * 2 + 0][k];
        float x1 = Xs[tx * 2 + 1][k];
#pragma unroll
        for (int i = 0; i < 4; ++i) {
            float w = Ws[ty * 4 + i][k];
            acc[i][0] += w * x0;
            acc[i][1] += w * x1;
        }
    }
#pragma unroll
    for (int i = 0; i < 4; ++i) {
        int r = r0 + ty * 4 + i;
        float bias = (r < 1600) ? bf[r] : bb[r - 1600];
#pragma unroll
        for (int j = 0; j < 2; ++j) {
            int s = s0 + tx * 2 + j;
            g_z[s * ZROWS + r] = acc[i][j] + bias;
        }
    }
}

// ---------------- 3. cluster biLSTM: 2 clusters of 16 CTAs, DSMEM h-exchange ----------------
// CTA = 25 hidden units. Weights register-resident (100 rows x 400 cols).
// Per step: matvec from local smem hs[p] -> gates -> push 25 h values into all
// 16 CTAs' hs[p^1] via st.shared::cluster -> barrier.cluster (release/acquire).
__global__ __launch_bounds__(256, 1) void lstm_kernel(
    const float* __restrict__ Whh_f, const float* __restrict__ Whh_b) {
    const int dir  = blockIdx.x >> 4;       // blocks 0-15: fwd cluster, 16-31: bwd cluster
    const uint32_t rank = ctarank_();       // 0..15
    const int u0   = (int)rank * UPC;       // first hidden unit of this CTA
    const float* Whh = dir ? Whh_b : Whh_f;

    const int tid   = threadIdx.x;
    const int chunk = tid & 1;              // 2 col chunks of 200
    const int rl    = tid >> 1;             // 0..127 local rows; valid < 100
    const bool valid = rl < 100;
    const int gate  = valid ? (rl / UPC) : 0;
    const int lu    = valid ? (rl % UPC) : 0;
    const int grow  = gate * 400 + u0 + lu;

    // preload Whh slice: 200 cols per thread = 50 float4 = 200 regs
    float4 w[50];
    {
        const float4* wp = (const float4*)(Whh + grow * 400 + chunk * 200);
#pragma unroll
        for (int j = 0; j < 50; ++j) w[j] = wp[j];
    }

    __shared__ __align__(16) float hs[2][400];
    __shared__ float zs[100];
    float c = 0.0f;  // cell state (threads 0..24)

    // init read buffer for step 0
    for (int i = tid; i < 400; i += 256) hs[0][i] = 0.0f;
    __syncthreads();

    const uint32_t hs_base = smem_u32(&hs[0][0]);

    for (int step = 0; step < SEQ; ++step) {
        const int s = dir ? (SEQ - 1 - step) : step;
        const int p = step & 1;

        // prefetch z_in (independent of h; overlaps matvec)
        float zp0, zp1, zp2, zp3;
        if (tid < UPC) {
            const float* zin = g_z + s * ZROWS + dir * 1600 + u0 + tid;
            zp0 = __ldg(zin);
            zp1 = __ldg(zin + 400);
            zp2 = __ldg(zin + 800);
            zp3 = __ldg(zin + 1200);
        }

        // matvec: row rl (gate,lu), cols chunk*200..+200 from hs[p]
        const float4* hv = (const float4*)(&hs[p][chunk * 200]);
        float ax = 0.f, ay = 0.f, az = 0.f, aw = 0.f;
#pragma unroll
        for (int j = 0; j < 50; ++j) {
            float4 v = hv[j];
            ax += w[j].x * v.x;
            ay += w[j].y * v.y;
            az += w[j].z * v.z;
            aw += w[j].w * v.w;
        }
        float val = (ax + ay) + (az + aw);
        val += __shfl_xor_sync(0xFFFFFFFFu, val, 1);   // combine the 2 col chunks
        if (chunk == 0 && valid) zs[rl] = val;
        __syncthreads();

        if (tid < UPC) {
            float zi = zs[0 * UPC + tid] + zp0;
            float zf = zs[1 * UPC + tid] + zp1;
            float zg = zs[2 * UPC + tid] + zp2;
            float zo = zs[3 * UPC + tid] + zp3;
            float iv = fast_sigmoid(zi);
            float fv = fast_sigmoid(zf);
            float gv = fast_tanh(zg);
            float ov = fast_sigmoid(zo);
            c = fv * c + iv * gv;
            float h = ov * fast_tanh(c);
            // persist for downstream projections
            __stcg(g_states + s * 800 + dir * 400 + u0 + tid, h);
            // push into hs[p^1][u0+tid] of every CTA in the cluster (incl. self)
            uint32_t dst = hs_base + (uint32_t)((p ^ 1) * 400 + u0 + tid) * 4u;
#pragma unroll
            for (uint32_t r = 0; r < NCLUST; ++r) st_dsmem_f32(dst, r, h);
        }
        cluster_sync_();   // release our DSMEM stores, acquire peers'
    }
}

// ---------------- 4. 12 projections: ptab[p][s][m] = sum_d W_proj[p][m][d]*states[s][d] ----------------
__global__ __launch_bounds__(224) void proj_kernel(const float* __restrict__ W_proj) {
    extern __shared__ float sm[];
    float* ws = sm;            // [100 k][200 m]
    float* st = sm + 20000;    // [16 s][100 k]

    const int p   = blockIdx.x;
    const int s0  = blockIdx.y * 16;
    const int tid = threadIdx.x;

    float acc[16];
#pragma unroll
    for (int i = 0; i < 16; ++i) acc[i] = 0.0f;

    for (int dc = 0; dc < 8; ++dc) {
        __syncthreads();
        for (int idx = tid; idx < 20000; idx += 224) {
            int m = idx / 100, k = idx % 100;
            ws[k * 200 + m] = W_proj[(p * 200 + m) * 800 + dc * 100 + k];
        }
        for (int idx = tid; idx < 1600; idx += 224) {
            int sl = idx / 100, k = idx % 100;
            st[sl * 100 + k] = g_states[(s0 + sl) * 800 + dc * 100 + k];
        }
        __syncthreads();

        if (tid < 200) {
            for (int k = 0; k < 100; k += 4) {
                float w0 = ws[(k + 0) * 200 + tid];
                float w1 = ws[(k + 1) * 200 + tid];
                float w2 = ws[(k + 2) * 200 + tid];
                float w3 = ws[(k + 3) * 200 + tid];
#pragma unroll
                for (int sl = 0; sl < 16; ++sl) {
                    float4 v = *(const float4*)(st + sl * 100 + k);
                    acc[sl] += w0 * v.x + w1 * v.y + w2 * v.z + w3 * v.w;
                }
            }
        }
    }
    if (tid < 200) {
#pragma unroll
        for (int sl = 0; sl < 16; ++sl)
            g_ptab[(p * TROWS + s0 + sl) * M + tid] = acc[sl];
    }
}

// ---------------- 5. scoring: warp per score (4 scores / warp) ----------------
template <int NR>
__device__ __forceinline__ float warp_score(const float* __restrict__ wsrow,
                                            const float* r0, const float* r1,
                                            const float* r2, const float* r3, int lane) {
    float acc = 0.0f;
#pragma unroll
    for (int it = 0; it < 4; ++it) {
        int m2 = it * 32 + lane;  // float2 index, valid < 100
        if (m2 < 100) {
            float2 a = ((const float2*)r0)[m2];
            float2 b = ((const float2*)r1)[m2];
            float sx = a.x + b.x, sy = a.y + b.y;
            if (NR > 2) {
                float2 cc = ((const float2*)r2)[m2];
                sx += cc.x; sy += cc.y;
            }
            if (NR > 3) {
                float2 d = ((const float2*)r3)[m2];
                sx += d.x; sy += d.y;
            }
            float2 w = ((const float2*)wsrow)[m2];
            acc += tanh_ap(sx) * w.x + tanh_ap(sy) * w.y;
        }
    }
    acc += __shfl_xor_sync(0xFFFFFFFFu, acc, 16);
    acc += __shfl_xor_sync(0xFFFFFFFFu, acc, 8);
    acc += __shfl_xor_sync(0xFFFFFFFFu, acc, 4);
    acc += __shfl_xor_sync(0xFFFFFFFFu, acc, 2);
    acc += __shfl_xor_sync(0xFFFFFFFFu, acc, 1);
    return acc;
}

#define GA (N_ARC / 4)
#define GS (N_SIB / 4)
#define GG (N_GP / 4)
#define GX (N_GSIB / 4)
#define TOTAL_GROUPS (GA + GS + GG + GX)

__global__ __launch_bounds__(256) void score_kernel(
    const int* __restrict__ arc_head, const int* __restrict__ arc_mod,
    const int* __restrict__ sib_head, const int* __restrict__ sib_mod, const int* __restrict__ sib_sib,
    const int* __restrict__ gp_head,  const int* __restrict__ gp_mod,  const int* __restrict__ gp_grand,
    const int* __restrict__ gsib_head, const int* __restrict__ gsib_mod,
    const int* __restrict__ gsib_sib,  const int* __restrict__ gsib_grand,
    const float* __restrict__ W_score, float* __restrict__ out) {
    int gw   = (blockIdx.x * blockDim.x + threadIdx.x) >> 5;
    int lane = threadIdx.x & 31;
    if (gw >= TOTAL_GROUPS) return;

    const float* tab = g_ptab;
    const float* t0 = tab + 0  * TROWS * M;
    const float* t1 = tab + 1  * TROWS * M;
    const float* t2 = tab + 2  * TROWS * M;
    const float* t3 = tab + 3  * TROWS * M;
    const float* t4 = tab + 4  * TROWS * M;
    const float* t5 = tab + 5  * TROWS * M;
    const float* t6 = tab + 6  * TROWS * M;
    const float* t7 = tab + 7  * TROWS * M;
    const float* t8 = tab + 8  * TROWS * M;
    const float* t9 = tab + 9  * TROWS * M;
    const float* t10 = tab + 10 * TROWS * M;
    const float* t11 = tab + 11 * TROWS * M;

    if (gw < GA) {
        int base = gw * 4;
#pragma unroll
        for (int k = 0; k < 4; ++k) {
            int i = base + k;
            float sc = warp_score<2>(W_score + 0 * M,
                                     t0 + arc_head[i] * M, t1 + arc_mod[i] * M,
                                     t0, t0, lane);
            if (lane == 0) out[i] = sc;
        }
    } else if (gw < GA + GS) {
        int base = (gw - GA) * 4;
#pragma unroll
        for (int k = 0; k < 4; ++k) {
            int i = base + k;
            float sc = warp_score<3>(W_score + 1 * M,
                                     t5 + sib_head[i] * M, t6 + sib_mod[i] * M,
                                     t7 + sib_sib[i] * M, t0, lane);
            if (lane == 0) out[N_ARC + i] = sc;
        }
    } else if (gw < GA + GS + GG) {
        int base = (gw - GA - GS) * 4;
#pragma unroll
        for (int k = 0; k < 4; ++k) {
            int i = base + k;
            float sc = warp_score<3>(W_score + 2 * M,
                                     t3 + gp_head[i] * M, t4 + gp_mod[i] * M,
                                     t2 + gp_grand[i] * M, t0, lane);
            if (lane == 0) out[N_ARC + N_SIB + i] = sc;
        }
    } else {
        int base = (gw - GA - GS - GG) * 4;
#pragma unroll
        for (int k = 0; k < 4; ++k) {
            int i = base + k;
            float sc = warp_score<4>(W_score + 3 * M,
                                     t8 + gsib_head[i] * M, t9 + gsib_mod[i] * M,
                                     t10 + gsib_sib[i] * M, t11 + gsib_grand[i] * M, lane);
            if (lane == 0) out[N_ARC + N_SIB + N_GP + i] = sc;
        }
    }
}

// ---------------- launch ----------------
extern "C" void kernel_launch(void* const* d_in, const int* in_sizes, int n_in,
                              void* d_out, int out_size) {
    const int*   words      = (const int*)d_in[0];
    const int*   tags       = (const int*)d_in[1];
    const int*   arc_head   = (const int*)d_in[2];
    const int*   arc_mod    = (const int*)d_in[3];
    const int*   sib_head   = (const int*)d_in[4];
    const int*   sib_mod    = (const int*)d_in[5];
    const int*   sib_sib    = (const int*)d_in[6];
    const int*   gp_head    = (const int*)d_in[7];
    const int*   gp_mod     = (const int*)d_in[8];
    const int*   gp_grand   = (const int*)d_in[9];
    const int*   gsib_head  = (const int*)d_in[10];
    const int*   gsib_mod   = (const int*)d_in[11];
    const int*   gsib_sib   = (const int*)d_in[12];
    const int*   gsib_grand = (const int*)d_in[13];
    const float* word_emb   = (const float*)d_in[14];
    const float* tag_emb    = (const float*)d_in[15];
    const float* Wih_f      = (const float*)d_in[16];
    const float* Whh_f      = (const float*)d_in[17];
    const float* b_f        = (const float*)d_in[18];
    const float* Wih_b      = (const float*)d_in[19];
    const float* Whh_b      = (const float*)d_in[20];
    const float* b_b        = (const float*)d_in[21];
    const float* W_proj     = (const float*)d_in[22];
    const float* W_score    = (const float*)d_in[23];
    const float* null_sib   = (const float*)d_in[24];
    float* out = (float*)d_out;

    static bool attr_done = false;
    if (!attr_done) {
        cudaFuncSetAttribute(proj_kernel, cudaFuncAttributeMaxDynamicSharedMemorySize, 90112);
        cudaFuncSetAttribute(lstm_kernel, cudaFuncAttributeNonPortableClusterSizeAllowed, 1);
        attr_done = true;
    }

    prep_kernel<<<1, 256>>>(null_sib);
    embed_kernel<<<SEQ, 128>>>(words, tags, word_emb, tag_emb);
    zin_kernel<<<dim3(50, 8), 256>>>(Wih_f, b_f, Wih_b, b_b);

    {
        cudaLaunchConfig_t cfg = {};
        cfg.gridDim  = dim3(2 * NCLUST, 1, 1);
        cfg.blockDim = dim3(256, 1, 1);
        cfg.dynamicSmemBytes = 0;
        cfg.stream = 0;
        cudaLaunchAttribute attrs[1];
        attrs[0].id = cudaLaunchAttributeClusterDimension;
        attrs[0].val.clusterDim.x = NCLUST;
        attrs[0].val.clusterDim.y = 1;
        attrs[0].val.clusterDim.z = 1;
        cfg.attrs = attrs;
        cfg.numAttrs = 1;
        (void)cudaLaunchKernelEx(&cfg, lstm_kernel, Whh_f, Whh_b);
    }

    proj_kernel<<<dim3(12, 16), 224, 86400>>>(W_proj);
    score_kernel<<<(TOTAL_GROUPS + 7) / 8, 256>>>(
        arc_head, arc_mod, sib_head, sib_mod, sib_sib,
        gp_head, gp_mod, gp_grand,
        gsib_head, gsib_mod, gsib_sib, gsib_grand,
        W_score, out);
}